// round 5
// baseline (speedup 1.0000x reference)
#include <cuda_runtime.h>
#include <cstdint>

#define M_TOTAL 16384
#define K_DIM   2048
#define E_DIM   64
#define TOPK    8

#define BM    128
#define BK    32
#define ASTR  68            // a_sm row stride in floats: 64 dup'd data + 4 pad
#define NTILE (K_DIM / BK)  // 64
#define NTHR  512

// One-time W transpose scratch: Wt[k][e]
__device__ float Wt_g[(size_t)K_DIM * E_DIM];

__global__ void transpose_w(const float* __restrict__ W, float* __restrict__ Wt) {
    int t = blockIdx.x * blockDim.x + threadIdx.x;   // 131072
    int e = t >> 11;            // 0..63
    int k = t & (K_DIM - 1);    // 0..2047
    Wt[(size_t)k * E_DIM + e] = W[(size_t)e * K_DIM + k];
}

// Packed fp32x2 FMA; per-lane rounding identical to scalar fmaf.
__device__ __forceinline__ float2 ffma2(float2 a, float2 b, float2 c) {
    float2 d;
    asm("fma.rn.f32x2 %0, %1, %2, %3;"
        : "=l"(reinterpret_cast<unsigned long long&>(d))
        : "l"(reinterpret_cast<unsigned long long&>(a)),
          "l"(reinterpret_cast<unsigned long long&>(b)),
          "l"(reinterpret_cast<unsigned long long&>(c)));
    return d;
}

// Fused logits GEMM (sequential ascending-k FMA chain per (m,e) — rounding
// identical to the round-3 passing kernel) + per-token top-8 + softmax.
// 512 threads/CTA, thread tile 4m x 4e: 16 warps/SM for latency hiding.
__global__ __launch_bounds__(NTHR, 1)
void router_fused(const float* __restrict__ X, const float* __restrict__ Wt,
                  float* __restrict__ logits,
                  float* __restrict__ wout, float* __restrict__ eout) {
    __shared__ float smem[BM * ASTR + BK * E_DIM];   // 42 KB static
    float* a_sm = smem;                // [BM][ASTR], dup'd: [m][2k]=[m][2k+1]=X[m][k]
    float* b_sm = smem + BM * ASTR;    // [BK][E_DIM]

    const int tid = threadIdx.x;
    const int eg  = tid & 15;    // 16 expert groups x 4 experts
    const int mg  = tid >> 4;    // 32 m groups x 4 rows
    const int m0  = blockIdx.x * BM;

    float2 acc[4][2];
    #pragma unroll
    for (int i = 0; i < 4; i++) { acc[i][0] = make_float2(0.f, 0.f); acc[i][1] = make_float2(0.f, 0.f); }

    // prefetch regs: a-tile = 1024 float4 -> 2/thread; b-tile = 512 float4 -> 1/thread
    float4 pa[2];
    float4 pb;
    int arow[2], aq[2];
    #pragma unroll
    for (int i = 0; i < 2; i++) { int f = tid + i * NTHR; arow[i] = f >> 3; aq[i] = f & 7; }

    #pragma unroll
    for (int i = 0; i < 2; i++)
        pa[i] = *reinterpret_cast<const float4*>(&X[(size_t)(m0 + arow[i]) * K_DIM + aq[i] * 4]);
    pb = reinterpret_cast<const float4*>(Wt)[tid];

    for (int t = 0; t < NTILE; t++) {
        #pragma unroll
        for (int i = 0; i < 2; i++) {
            float4 v = pa[i];
            *reinterpret_cast<float4*>(&a_sm[arow[i] * ASTR + aq[i] * 8]) =
                make_float4(v.x, v.x, v.y, v.y);
            *reinterpret_cast<float4*>(&a_sm[arow[i] * ASTR + aq[i] * 8 + 4]) =
                make_float4(v.z, v.z, v.w, v.w);
        }
        reinterpret_cast<float4*>(b_sm)[tid] = pb;
        __syncthreads();

        if (t + 1 < NTILE) {
            int kn = (t + 1) * BK;
            #pragma unroll
            for (int i = 0; i < 2; i++)
                pa[i] = *reinterpret_cast<const float4*>(
                    &X[(size_t)(m0 + arow[i]) * K_DIM + kn + aq[i] * 4]);
            pb = reinterpret_cast<const float4*>(&Wt[(size_t)kn * E_DIM])[tid];
        }

        #pragma unroll
        for (int kk = 0; kk < BK; kk += 2) {
            float4 a4[4];
            #pragma unroll
            for (int i = 0; i < 4; i++)
                a4[i] = *reinterpret_cast<const float4*>(&a_sm[(mg * 4 + i) * ASTR + kk * 2]);

            #pragma unroll
            for (int s = 0; s < 2; s++) {
                float4 b0 = *reinterpret_cast<const float4*>(&b_sm[(kk + s) * E_DIM + eg * 4]);
                float2 bp0 = make_float2(b0.x, b0.y);
                float2 bp1 = make_float2(b0.z, b0.w);
                #pragma unroll
                for (int i = 0; i < 4; i++) {
                    float2 ap = s ? make_float2(a4[i].z, a4[i].w)
                                  : make_float2(a4[i].x, a4[i].y);
                    acc[i][0] = ffma2(ap, bp0, acc[i][0]);
                    acc[i][1] = ffma2(ap, bp1, acc[i][1]);
                }
            }
        }
        __syncthreads();
    }

    // Epilogue: write logits (global) + stage rows in smem for topk.
    #pragma unroll
    for (int i = 0; i < 4; i++) {
        int m = mg * 4 + i;
        float4 o = make_float4(acc[i][0].x, acc[i][0].y, acc[i][1].x, acc[i][1].y);
        *reinterpret_cast<float4*>(&logits[(size_t)(m0 + m) * E_DIM + eg * 4]) = o;
        *reinterpret_cast<float4*>(&smem[m * ASTR + eg * 4]) = o;
    }
    __syncthreads();

    // Top-8 + softmax: one thread per token (threads 0..127).
    if (tid < BM) {
        const float* row = &smem[tid * ASTR];
        float tv[TOPK];
        int   ti[TOPK];
        #pragma unroll
        for (int i = 0; i < TOPK; i++) { tv[i] = -3.4e38f; ti[i] = 0; }

        #pragma unroll
        for (int q = 0; q < E_DIM / 4; q++) {
            float4 v4 = *reinterpret_cast<const float4*>(&row[q * 4]);
            float vs[4] = {v4.x, v4.y, v4.z, v4.w};
            #pragma unroll
            for (int u = 0; u < 4; u++) {
                float v = vs[u];
                int   e = q * 4 + u;
                if (v > tv[TOPK - 1]) {
                    tv[TOPK - 1] = v; ti[TOPK - 1] = e;
                    #pragma unroll
                    for (int j = TOPK - 1; j > 0; j--) {
                        if (tv[j] > tv[j - 1]) {   // strict: ties keep earlier index
                            float tf = tv[j]; tv[j] = tv[j - 1]; tv[j - 1] = tf;
                            int   tx = ti[j]; ti[j] = ti[j - 1]; ti[j - 1] = tx;
                        }
                    }
                }
            }
        }

        float mx = tv[0];
        float ev[TOPK], ssum = 0.f;
        #pragma unroll
        for (int i = 0; i < TOPK; i++) { ev[i] = __expf(tv[i] - mx); ssum += ev[i]; }
        float inv = 1.f / ssum;
        size_t tok = (size_t)(m0 + tid);
        #pragma unroll
        for (int i = 0; i < TOPK; i++) {
            wout[tok * TOPK + i] = ev[i] * inv;
            eout[tok * TOPK + i] = (float)ti[i];
        }
    }
}

extern "C" void kernel_launch(void* const* d_in, const int* in_sizes, int n_in,
                              void* d_out, int out_size) {
    const float* X = (const float*)d_in[0];   // [4,4096,2048] fp32
    const float* W = (const float*)d_in[1];   // [64,2048]     fp32

    float* out    = (float*)d_out;
    float* logits = out;                                   // 16384*64
    float* wts    = out + (size_t)M_TOTAL * E_DIM;         // 16384*8
    float* exps   = wts + (size_t)M_TOTAL * TOPK;          // 16384*8

    float* Wt;
    cudaGetSymbolAddress((void**)&Wt, Wt_g);

    transpose_w<<<(K_DIM * E_DIM) / 256, 256>>>(W, Wt);
    router_fused<<<M_TOTAL / BM, NTHR>>>(X, Wt, logits, wts, exps);
}

// round 6
// speedup vs baseline: 1.4670x; 1.4670x over previous
#include <cuda_runtime.h>
#include <cstdint>

#define M_TOTAL 16384
#define K_DIM   2048
#define E_DIM   64
#define TOPK    8

#define BM    128
#define BK    32
#define NTILE (K_DIM / BK)   // 64
#define NTHR  256
#define LSTR  68             // epilogue logits row stride (floats)

// One-time W transpose scratch: Wt[k][e]
__device__ float Wt_g[(size_t)K_DIM * E_DIM];

__global__ void transpose_w(const float* __restrict__ W, float* __restrict__ Wt) {
    int t = blockIdx.x * blockDim.x + threadIdx.x;   // 131072
    int e = t >> 11;
    int k = t & (K_DIM - 1);
    Wt[(size_t)k * E_DIM + e] = W[(size_t)e * K_DIM + k];
}

// Packed fp32x2 FMA; per-lane rounding identical to scalar fmaf.
__device__ __forceinline__ float2 ffma2(float2 a, float2 b, float2 c) {
    float2 d;
    asm("fma.rn.f32x2 %0, %1, %2, %3;"
        : "=l"(reinterpret_cast<unsigned long long&>(d))
        : "l"(reinterpret_cast<unsigned long long&>(a)),
          "l"(reinterpret_cast<unsigned long long&>(b)),
          "l"(reinterpret_cast<unsigned long long&>(c)));
    return d;
}

// Fused logits GEMM + top-8 + softmax.
// Warp w: experts e0 = (w&3)*16 (uniform across lanes -> broadcast b loads),
//         m rows  = (w>>2)*64 + lane + {0,32}.
// a_sm is k-major [BK][BM] with XOR swizzle col = m ^ (4*(k>>2)):
//   - staging STS.32 conflict-free, mainloop LDS.32 conflict-free (1 wf).
// Sequential ascending-k FMA chain per (m,e) -> bit-identical to round-3 kernel.
__global__ __launch_bounds__(NTHR, 1)
void router_fused(const float* __restrict__ X, const float* __restrict__ Wt,
                  float* __restrict__ logits,
                  float* __restrict__ wout, float* __restrict__ eout) {
    __shared__ float smem[BM * LSTR];          // 8704 floats = 34.8 KB (epilogue size)
    float* a_sm = smem;                        // [BK][BM] swizzled (4096 floats)
    float* b_sm = smem + BK * BM;              // [BK][E_DIM] (2048 floats)

    const int tid  = threadIdx.x;
    const int w    = tid >> 5;
    const int lane = tid & 31;
    const int e0   = (w & 3) * 16;
    const int m1   = (w >> 2) * 64 + lane;
    const int m2   = m1 + 32;
    const int m0   = blockIdx.x * BM;

    float2 acc[2][8];
    #pragma unroll
    for (int r = 0; r < 2; r++)
        #pragma unroll
        for (int j = 0; j < 8; j++) acc[r][j] = make_float2(0.f, 0.f);

    // prefetch registers: a tile = 1024 float4 -> 4/thread; b tile = 512 float4 -> 2/thread
    float4 pa[4];
    float4 pb[2];
    int am[4], aq[4];
    #pragma unroll
    for (int i = 0; i < 4; i++) { int f = tid + i * NTHR; am[i] = f >> 3; aq[i] = f & 7; }

    #pragma unroll
    for (int i = 0; i < 4; i++)
        pa[i] = *reinterpret_cast<const float4*>(&X[(size_t)(m0 + am[i]) * K_DIM + aq[i] * 4]);
    pb[0] = reinterpret_cast<const float4*>(Wt)[tid];
    pb[1] = reinterpret_cast<const float4*>(Wt)[tid + 256];

    for (int t = 0; t < NTILE; t++) {
        // ---- stage a (k-major, swizzled) ----
        #pragma unroll
        for (int i = 0; i < 4; i++) {
            int q   = aq[i];
            int col = am[i] ^ (4 * q);          // SW(k) = 4*(k>>2) = 4*q for k=4q+j
            float vs[4] = {pa[i].x, pa[i].y, pa[i].z, pa[i].w};
            #pragma unroll
            for (int j = 0; j < 4; j++)
                a_sm[(4 * q + j) * BM + col] = vs[j];
        }
        // ---- stage b (direct copy) ----
        reinterpret_cast<float4*>(b_sm)[tid]       = pb[0];
        reinterpret_cast<float4*>(b_sm)[tid + 256] = pb[1];
        __syncthreads();

        // ---- prefetch next tile ----
        if (t + 1 < NTILE) {
            int kn = (t + 1) * BK;
            #pragma unroll
            for (int i = 0; i < 4; i++)
                pa[i] = *reinterpret_cast<const float4*>(
                    &X[(size_t)(m0 + am[i]) * K_DIM + kn + aq[i] * 4]);
            pb[0] = reinterpret_cast<const float4*>(&Wt[(size_t)kn * E_DIM])[tid];
            pb[1] = reinterpret_cast<const float4*>(&Wt[(size_t)kn * E_DIM])[tid + 256];
        }

        // ---- mainloop ----
        #pragma unroll
        for (int kk = 0; kk < BK; kk++) {
            const int sw = 4 * (kk >> 2);
            // b: 4 uniform LDS.128 (broadcast, 1 wf each)
            float4 b4[4];
            #pragma unroll
            for (int j = 0; j < 4; j++)
                b4[j] = *reinterpret_cast<const float4*>(&b_sm[kk * E_DIM + e0 + 4 * j]);
            // a: 2 coalesced LDS.32, dup to (a,a) in registers
            float a1 = a_sm[kk * BM + (m1 ^ sw)];
            float a2 = a_sm[kk * BM + (m2 ^ sw)];
            float2 ap1 = make_float2(a1, a1);
            float2 ap2 = make_float2(a2, a2);
            #pragma unroll
            for (int j = 0; j < 4; j++) {
                float2 blo = make_float2(b4[j].x, b4[j].y);
                float2 bhi = make_float2(b4[j].z, b4[j].w);
                acc[0][2 * j]     = ffma2(ap1, blo, acc[0][2 * j]);
                acc[0][2 * j + 1] = ffma2(ap1, bhi, acc[0][2 * j + 1]);
                acc[1][2 * j]     = ffma2(ap2, blo, acc[1][2 * j]);
                acc[1][2 * j + 1] = ffma2(ap2, bhi, acc[1][2 * j + 1]);
            }
        }
        __syncthreads();
    }

    // ---- epilogue: logits to global + stage rows in smem for topk ----
    #pragma unroll
    for (int r = 0; r < 2; r++) {
        int m = r ? m2 : m1;
        #pragma unroll
        for (int j = 0; j < 4; j++) {
            float4 v = make_float4(acc[r][2 * j].x, acc[r][2 * j].y,
                                   acc[r][2 * j + 1].x, acc[r][2 * j + 1].y);
            *reinterpret_cast<float4*>(&logits[(size_t)(m0 + m) * E_DIM + e0 + 4 * j]) = v;
            *reinterpret_cast<float4*>(&smem[m * LSTR + e0 + 4 * j]) = v;
        }
    }
    __syncthreads();

    // ---- top-8 + softmax: one thread per token ----
    if (tid < BM) {
        const float* row = &smem[tid * LSTR];
        float tv[TOPK];
        int   ti[TOPK];
        #pragma unroll
        for (int i = 0; i < TOPK; i++) { tv[i] = -3.4e38f; ti[i] = 0; }

        #pragma unroll
        for (int q = 0; q < E_DIM / 4; q++) {
            float4 v4 = *reinterpret_cast<const float4*>(&row[q * 4]);
            float vs[4] = {v4.x, v4.y, v4.z, v4.w};
            #pragma unroll
            for (int u = 0; u < 4; u++) {
                float v = vs[u];
                int   e = q * 4 + u;
                if (v > tv[TOPK - 1]) {
                    tv[TOPK - 1] = v; ti[TOPK - 1] = e;
                    #pragma unroll
                    for (int j = TOPK - 1; j > 0; j--) {
                        if (tv[j] > tv[j - 1]) {   // strict: ties keep earlier index
                            float tf = tv[j]; tv[j] = tv[j - 1]; tv[j - 1] = tf;
                            int   tx = ti[j]; ti[j] = ti[j - 1]; ti[j - 1] = tx;
                        }
                    }
                }
            }
        }

        float mx = tv[0];
        float ev[TOPK], ssum = 0.f;
        #pragma unroll
        for (int i = 0; i < TOPK; i++) { ev[i] = __expf(tv[i] - mx); ssum += ev[i]; }
        float inv = 1.f / ssum;
        size_t tok = (size_t)(m0 + tid);
        #pragma unroll
        for (int i = 0; i < TOPK; i++) {
            wout[tok * TOPK + i] = ev[i] * inv;
            eout[tok * TOPK + i] = (float)ti[i];
        }
    }
}

extern "C" void kernel_launch(void* const* d_in, const int* in_sizes, int n_in,
                              void* d_out, int out_size) {
    const float* X = (const float*)d_in[0];   // [4,4096,2048] fp32
    const float* W = (const float*)d_in[1];   // [64,2048]     fp32

    float* out    = (float*)d_out;
    float* logits = out;                                   // 16384*64
    float* wts    = out + (size_t)M_TOTAL * E_DIM;         // 16384*8
    float* exps   = wts + (size_t)M_TOTAL * TOPK;          // 16384*8

    float* Wt;
    cudaGetSymbolAddress((void**)&Wt, Wt_g);

    transpose_w<<<(K_DIM * E_DIM) / 256, 256>>>(W, Wt);
    router_fused<<<M_TOTAL / BM, NTHR>>>(X, Wt, logits, wts, exps);
}